// round 12
// baseline (speedup 1.0000x reference)
#include <cuda_runtime.h>
#include <cstdint>

// Problem constants (fixed shapes per reference)
#define B_DIM 4
#define P_DIM 2
#define T_DIM 1024
#define F_DIM 1024
#define D_DIM 16
#define CHUNK 128
#define NCHUNK (F_DIM / CHUNK)   // 8
#define T_PER_BLOCK 8
#define NBLOCKS (B_DIM * D_DIM * P_DIM * (T_DIM / T_PER_BLOCK))  // 16384

// Per-(b,d,chunk) integer shifts. 4*16*8 = 512 ints.
__device__ int g_shift[B_DIM * D_DIM * NCHUNK];
// Intra-launch sync state; self-resetting so every graph replay is identical.
__device__ unsigned g_flag = 0;   // 1 = shifts published
__device__ unsigned g_done = 0;  // completed-block counter

// ---------------------------------------------------------------------------
// Single kernel. Block 0 computes the 512 chunk shifts (same sequential
// rounded-product order that gave rel_err == 0.0) and release-publishes them;
// other blocks acquire-spin (only wave-1 blocks ever actually spin).
// Gather body is identical to the 83.2us two-kernel version.
// grid = 16384 blocks, 256 threads. Warp w handles chunk w (shift warp-uniform).
// ---------------------------------------------------------------------------
__global__ __launch_bounds__(256)
void dedisp_kernel(const float4* __restrict__ x,
                   float4*       __restrict__ out,
                   const float*  __restrict__ dm,
                   const float*  __restrict__ df,
                   float*        __restrict__ delays)
{
    const int bi = blockIdx.x;
    const int tb = bi & (T_DIM / T_PER_BLOCK - 1);   // 0..127
    const int p  = (bi >> 7) & (P_DIM - 1);
    const int d  = (bi >> 8) & (D_DIM - 1);
    const int b  = bi >> 12;
    const int bd = b * D_DIM + d;

    const int tid = threadIdx.x;          // 0..255, f4 index
    const int c   = tid >> 5;             // chunk = warp id

    // --- delays tail (independent of shifts): 64 blocks, done pre-wait ----
    if (p == 0 && tb == 0) {
        const float dmv = dm[bd];
        float* drow = delays + (size_t)bd * F_DIM;
        #pragma unroll
        for (int j = 0; j < 4; j++) {
            const int f = tid + j * 256;                 // coalesced
            drow[f] = __fmul_rn(dmv, df[f]);
        }
    }

    if (bi == 0) {
        // ---- compute all 512 shifts: 2 independent chains per thread -----
        #pragma unroll
        for (int r = 0; r < 2; r++) {
            const int idx = tid + r * 256;               // 0..511
            const int sbd = idx >> 3;
            const int sc  = idx & (NCHUNK - 1);
            const float dmv = dm[sbd];
            const float* base = df + sc * CHUNK;
            float sum = 0.0f;
            #pragma unroll 16
            for (int i = 0; i < CHUNK; i++)
                sum = __fadd_rn(sum, __fmul_rn(dmv, base[i]));
            const float mean = __fmul_rn(sum, 0.0078125f);   // exact *2^-7
            int s = (int)truncf(mean);
            if (s < 0) s = 0;
            g_shift[idx] = s & (T_DIM - 1);
        }
        __syncthreads();                  // shifts visible within block 0
        if (tid == 0) {
            asm volatile("st.release.gpu.global.u32 [%0], %1;"
                         :: "l"(&g_flag), "r"(1u) : "memory");
        }
    } else {
        // ---- one thread spins, rest wait at the barrier -------------------
        if (tid == 0) {
            unsigned f;
            do {
                asm volatile("ld.acquire.gpu.global.u32 %0, [%1];"
                             : "=r"(f) : "l"(&g_flag) : "memory");
                if (!f) __nanosleep(64);
            } while (!f);
        }
        __syncthreads();
    }

    const int s = g_shift[bd * NCHUNK + c];

    // --- gather-copy: 8 float4 rows per thread (identical to R7) ----------
    const int F4 = F_DIM / 4;             // 256 float4 per row

    const float4* __restrict__ xrow =
        x + (size_t)(b * P_DIM + p) * T_DIM * F4;

    float4* __restrict__ orow =
        out + ((size_t)(bd * P_DIM + p) * T_DIM
               + (size_t)tb * T_PER_BLOCK) * F4 + tid;

    const int t0 = tb * T_PER_BLOCK;

    #pragma unroll
    for (int k = 0; k < T_PER_BLOCK; k++) {
        int ts = t0 + k + s;
        if (ts >= T_DIM) ts -= T_DIM;     // s < 1024, t < 1024 -> one subtract
        orow[k * F4] = __ldg(&xrow[(size_t)ts * F4 + tid]);
    }

    // --- self-reset: last finishing block zeroes flag + counter -----------
    __syncthreads();
    if (tid == 0) {
        const unsigned prev = atomicAdd(&g_done, 1u);
        if (prev == (unsigned)(NBLOCKS - 1)) {
            g_done = 0;
            __threadfence();
            g_flag = 0;                   // next replay sees pristine state
        }
    }
}

// ---------------------------------------------------------------------------
// Launch: one kernel, one graph node.
// ---------------------------------------------------------------------------
extern "C" void kernel_launch(void* const* d_in, const int* in_sizes, int n_in,
                              void* d_out, int out_size)
{
    const float* x  = (const float*)d_in[0];   // (4,2,1024,1024)
    const float* dm = (const float*)d_in[1];   // (4,16)
    const float* df = (const float*)d_in[2];   // (1024,)

    float* out = (float*)d_out;
    // Output layout: dedispersed (4,16,2,1024,1024) then delays (4,16,1024)
    float* delays = out + (size_t)B_DIM * D_DIM * P_DIM * T_DIM * F_DIM;

    dedisp_kernel<<<NBLOCKS, 256>>>((const float4*)x, (float4*)out,
                                    dm, df, delays);
}

// round 13
// speedup vs baseline: 1.0034x; 1.0034x over previous
#include <cuda_runtime.h>
#include <cstdint>

// Problem constants (fixed shapes per reference)
#define B_DIM 4
#define P_DIM 2
#define T_DIM 1024
#define F_DIM 1024
#define D_DIM 16
#define CHUNK 128
#define NCHUNK (F_DIM / CHUNK)   // 8
#define T_PER_BLOCK 8

// Per-(b,d,chunk) integer shifts. 4*16*8 = 512 ints.
__device__ int g_shift[B_DIM * D_DIM * NCHUNK];

// ---------------------------------------------------------------------------
// Kernel 1 (minimal): one block, 512 threads; thread (bd, c) runs the
// sequential rounded-product chain that exactly reproduces the reference's
// trunc(chunk_mean) (rel_err == 0.0 verified with this exact order).
// No smem, no barriers, no other outputs.
// ---------------------------------------------------------------------------
__global__ void dedisp_prep_kernel(const float* __restrict__ dm,
                                   const float* __restrict__ df)
{
    const int idx = threadIdx.x;          // 0..511
    const int bd  = idx >> 3;             // (b*16 + d)
    const int c   = idx & (NCHUNK - 1);   // chunk

    const float dmv = dm[bd];
    const float* base = df + c * CHUNK;

    float sum = 0.0f;
    #pragma unroll 16
    for (int i = 0; i < CHUNK; i++)
        sum = __fadd_rn(sum, __fmul_rn(dmv, base[i]));  // round mul, then add

    const float mean = __fmul_rn(sum, 0.0078125f);       // exact *2^-7
    int s = (int)truncf(mean);
    if (s < 0) s = 0;
    g_shift[idx] = s & (T_DIM - 1);
}

// ---------------------------------------------------------------------------
// Kernel 2: the gather-copy, byte-identical memory behavior to the 83.2us
// R7 kernel (float4 __ldg loads, plain float4 stores).
// grid = B*D*P*(T/T_PER_BLOCK) = 16384 blocks, 256 threads.
// Warp w handles chunk w -> shift is warp-uniform.
// The 64 (p==0, tb==0) blocks additionally write the delays output tail
// (coalesced, independent of g_shift).
// ---------------------------------------------------------------------------
__global__ __launch_bounds__(256)
void dedisp_gather_kernel(const float4* __restrict__ x,
                          float4*       __restrict__ out,
                          const float*  __restrict__ dm,
                          const float*  __restrict__ df,
                          float*        __restrict__ delays)
{
    const int bi = blockIdx.x;
    const int tb = bi & (T_DIM / T_PER_BLOCK - 1);   // 0..127
    const int p  = (bi >> 7) & (P_DIM - 1);
    const int d  = (bi >> 8) & (D_DIM - 1);
    const int b  = bi >> 12;
    const int bd = b * D_DIM + d;

    const int tid = threadIdx.x;          // 0..255, f4 index
    const int c   = tid >> 5;             // chunk = warp id

    // delays tail: 64 blocks, coalesced, no dependency on shifts
    if (p == 0 && tb == 0) {
        const float dmv = dm[bd];
        float* drow = delays + (size_t)bd * F_DIM;
        #pragma unroll
        for (int j = 0; j < 4; j++) {
            const int f = tid + j * 256;
            drow[f] = __fmul_rn(dmv, df[f]);
        }
    }

    const int s = g_shift[bd * NCHUNK + c];

    const int F4 = F_DIM / 4;             // 256 float4 per row

    const float4* __restrict__ xrow =
        x + (size_t)(b * P_DIM + p) * T_DIM * F4;

    float4* __restrict__ orow =
        out + ((size_t)(bd * P_DIM + p) * T_DIM
               + (size_t)tb * T_PER_BLOCK) * F4 + tid;

    const int t0 = tb * T_PER_BLOCK;

    #pragma unroll
    for (int k = 0; k < T_PER_BLOCK; k++) {
        int ts = t0 + k + s;
        if (ts >= T_DIM) ts -= T_DIM;     // s < 1024, t < 1024 -> one subtract
        orow[k * F4] = __ldg(&xrow[(size_t)ts * F4 + tid]);
    }
}

// ---------------------------------------------------------------------------
// Launch: two plain sequential graph nodes (no PDL, no device-side sync).
// ---------------------------------------------------------------------------
extern "C" void kernel_launch(void* const* d_in, const int* in_sizes, int n_in,
                              void* d_out, int out_size)
{
    const float* x  = (const float*)d_in[0];   // (4,2,1024,1024)
    const float* dm = (const float*)d_in[1];   // (4,16)
    const float* df = (const float*)d_in[2];   // (1024,)

    float* out = (float*)d_out;
    // Output layout: dedispersed (4,16,2,1024,1024) then delays (4,16,1024)
    float* delays = out + (size_t)B_DIM * D_DIM * P_DIM * T_DIM * F_DIM;

    dedisp_prep_kernel<<<1, 512>>>(dm, df);

    const int nblocks = B_DIM * D_DIM * P_DIM * (T_DIM / T_PER_BLOCK); // 16384
    dedisp_gather_kernel<<<nblocks, 256>>>((const float4*)x, (float4*)out,
                                           dm, df, delays);
}